// round 14
// baseline (speedup 1.0000x reference)
#include <cuda_runtime.h>
#include <cuda_bf16.h>
#include <math.h>
#include <stdint.h>

#define N_NODES 100000
#define N_EDGES 600000
#define H 128
#define R 16
#define SCALING 2.0f
#define LN_EPS 1e-5f

#define SCAN_CHUNK 512
#define SCAN_NB ((N_NODES + SCAN_CHUNK - 1) / SCAN_CHUNK)   // 196

#define TILE_M 128
#define NT_TILES ((N_NODES + TILE_M - 1) / TILE_M)          // 782
#define FGRID 148
#define FTHREADS 512

#define QPAD 516                      // words per (v,q) staging plane (4*128 + 4 pad)
#define PLANE_W (3 * 8 * QPAD)        // words per staging set = 12384 (49536 B)
#define BUFCAP 128                    // edge records per warp buffer

// fused smem layout (bytes): 3 weight images + 2x staging sets + edge buffer
#define SMB_W    0                    // 3 x 32KB = 98304
#define SMB_STG  98304                // 2 x 49536 = 99072
#define SMB_MB   197376
#define SMB_GB   197888
#define SMB_GA   198400
#define SMB_BE   198912
#define SMB_S1   199424               // [8][64] f32
#define SMB_S2   201472
#define SMB_EBUF 203520               // 16 warps x 128 int2 = 16384
#define FUSED_SMEM 219904

// ---------- static device scratch ----------
__device__ int   g_deg[N_NODES];      // zero-init; scatter restores to zero each call
__device__ int   g_off[N_NODES + 1];
__device__ float g_dinv[N_NODES];
__device__ int2  g_erec[N_EDGES];     // packed (src, __float_as_int(dinv[src]))
__device__ int   g_bsum[256];

// ---------- helpers ----------
__device__ __forceinline__ unsigned pack_bf2(float e0, float e1) {
    unsigned r;
    asm("cvt.rn.bf16x2.f32 %0, %1, %2;" : "=r"(r) : "f"(e1), "f"(e0));  // lo=e0, hi=e1
    return r;
}
__device__ __forceinline__ uint2 split_bf2(float e0, float e1) {
    unsigned hi = pack_bf2(e0, e1);
    float h0 = __uint_as_float(hi << 16);
    float h1 = __uint_as_float(hi & 0xffff0000u);
    unsigned lo = pack_bf2(e0 - h0, e1 - h1);
    return make_uint2(hi, lo);
}
__device__ __forceinline__ void mma16816(float* d, const unsigned* a, const unsigned* b) {
    asm volatile(
        "mma.sync.aligned.m16n8k16.row.col.f32.bf16.bf16.f32 "
        "{%0,%1,%2,%3}, {%4,%5,%6,%7}, {%8,%9}, {%0,%1,%2,%3};"
        : "+f"(d[0]), "+f"(d[1]), "+f"(d[2]), "+f"(d[3])
        : "r"(a[0]), "r"(a[1]), "r"(a[2]), "r"(a[3]), "r"(b[0]), "r"(b[1]));
}
__device__ __forceinline__ int stg_i(int v, int q, int g, int tw) {
    return (v * 8 + q) * QPAD + g * 128 + tw;
}

// ---------- 1. in-degree histogram ----------
__global__ void hist_kernel(const int* __restrict__ col) {
    int e = blockIdx.x * blockDim.x + threadIdx.x;
    if (e < N_EDGES) atomicAdd(&g_deg[col[e]], 1);
}

// ---------- 2. parallel 3-pass scan (coalesced) ----------
__global__ void scan_pass1() {
    __shared__ int sh[SCAN_CHUNK];
    int i = blockIdx.x * SCAN_CHUNK + threadIdx.x;
    sh[threadIdx.x] = (i < N_NODES) ? g_deg[i] : 0;
    __syncthreads();
    for (int off = SCAN_CHUNK / 2; off > 0; off >>= 1) {
        if (threadIdx.x < off) sh[threadIdx.x] += sh[threadIdx.x + off];
        __syncthreads();
    }
    if (threadIdx.x == 0) g_bsum[blockIdx.x] = sh[0];
}
__global__ void scan_pass2() {
    __shared__ int sh[256];
    int t = threadIdx.x;
    int v = (t < SCAN_NB) ? g_bsum[t] : 0;
    sh[t] = v;
    __syncthreads();
    for (int off = 1; off < 256; off <<= 1) {
        int add = (t >= off) ? sh[t - off] : 0;
        __syncthreads();
        sh[t] += add;
        __syncthreads();
    }
    if (t < SCAN_NB) g_bsum[t] = sh[t] - v;   // exclusive
    if (t == 255) g_off[N_NODES] = sh[255];
}
__global__ void scan_pass3() {       // + dinv folded in
    __shared__ int sh[SCAN_CHUNK];
    int i = blockIdx.x * SCAN_CHUNK + threadIdx.x;
    int v = (i < N_NODES) ? g_deg[i] : 0;
    sh[threadIdx.x] = v;
    __syncthreads();
    for (int off = 1; off < SCAN_CHUNK; off <<= 1) {
        int t = (threadIdx.x >= off) ? sh[threadIdx.x - off] : 0;
        __syncthreads();
        sh[threadIdx.x] += t;
        __syncthreads();
    }
    if (i < N_NODES) {
        g_off[i]  = g_bsum[blockIdx.x] + sh[threadIdx.x] - v;
        g_dinv[i] = rsqrtf((float)(v + 1));
    }
}

// ---------- 3. bucket edges by target; records (src, dinv[src]); zeroes g_deg ----------
__global__ void scatter_kernel(const int* __restrict__ row, const int* __restrict__ col) {
    int e = blockIdx.x * blockDim.x + threadIdx.x;
    if (e < N_EDGES) {
        int c = col[e];
        int r = row[e];
        int p = atomicAdd(&g_deg[c], -1) - 1;    // restores g_deg to 0
        g_erec[g_off[c] + p] = make_int2(r, __float_as_int(g_dinv[r]));
    }
}

// ---------- gather one 64-row half into a staging set (R12-exact, unroll 1) ----------
__device__ __forceinline__ void gather_half(
    int base, unsigned* stgbuf, int2* ebuf,
    const float4* __restrict__ x4, int w, int lane)
{
    int n0  = base + w * 4;
    int n0c = (n0     < N_NODES) ? n0     : N_NODES;
    int n4c = (n0 + 4 < N_NODES) ? n0 + 4 : N_NODES;
    int begAll = g_off[n0c];
    int endAll = g_off[n4c];
    int cnt    = endAll - begAll;
    bool fast  = (cnt <= BUFCAP);
    __syncwarp();                       // WAR: prior reads of ebuf done
    if (fast) {
#pragma unroll 1
        for (int cb = 0; cb < cnt; cb += 32)
            if (cb + lane < cnt) ebuf[cb + lane] = g_erec[begAll + cb + lane];
        __syncwarp();
    }
#pragma unroll 1
    for (int i = 0; i < 4; i++) {
        int r_loc = w * 4 + i;
        int node  = base + r_loc;
        float4 xc = make_float4(0.f, 0.f, 0.f, 0.f);
        float m0 = 0.f, m1 = 0.f, m2 = 0.f, m3 = 0.f;
        if (node < N_NODES) {
            float4 accA = make_float4(0.f, 0.f, 0.f, 0.f);
            float4 accB = make_float4(0.f, 0.f, 0.f, 0.f);
            float4 accC = make_float4(0.f, 0.f, 0.f, 0.f);
            float4 accD = make_float4(0.f, 0.f, 0.f, 0.f);
            int beg = g_off[node], end = g_off[node + 1];
            if (fast) {
                int jb = beg - begAll, je = end - begAll;
#pragma unroll 1
                for (int j = jb; j < je; j += 4) {
                    int2 rA = ebuf[j];
                    int2 rB = (j + 1 < je) ? ebuf[j + 1] : make_int2(0, 0);
                    int2 rC = (j + 2 < je) ? ebuf[j + 2] : make_int2(0, 0);
                    int2 rD = (j + 3 < je) ? ebuf[j + 3] : make_int2(0, 0);
                    float4 vA = x4[rA.x * 32 + lane];
                    float4 vB = x4[rB.x * 32 + lane];
                    float4 vC = x4[rC.x * 32 + lane];
                    float4 vD = x4[rD.x * 32 + lane];
                    float wA = __int_as_float(rA.y), wB = __int_as_float(rB.y);
                    float wC = __int_as_float(rC.y), wD = __int_as_float(rD.y);
                    accA.x += wA * vA.x; accA.y += wA * vA.y; accA.z += wA * vA.z; accA.w += wA * vA.w;
                    accB.x += wB * vB.x; accB.y += wB * vB.y; accB.z += wB * vB.z; accB.w += wB * vB.w;
                    accC.x += wC * vC.x; accC.y += wC * vC.y; accC.z += wC * vC.z; accC.w += wC * vC.w;
                    accD.x += wD * vD.x; accD.y += wD * vD.y; accD.z += wD * vD.z; accD.w += wD * vD.w;
                }
            } else {
#pragma unroll 1
                for (int e = beg; e < end; e += 2) {
                    int2 rA = g_erec[e];
                    int2 rB = (e + 1 < end) ? g_erec[e + 1] : make_int2(0, 0);
                    float4 vA = x4[rA.x * 32 + lane];
                    float4 vB = x4[rB.x * 32 + lane];
                    float wA = __int_as_float(rA.y), wB = __int_as_float(rB.y);
                    accA.x += wA * vA.x; accA.y += wA * vA.y; accA.z += wA * vA.z; accA.w += wA * vA.w;
                    accB.x += wB * vB.x; accB.y += wB * vB.y; accB.z += wB * vB.z; accB.w += wB * vB.w;
                }
            }
            float dc = g_dinv[node];
            float sc = dc / (float)(end - beg + 1);
            xc = x4[node * 32 + lane];
            m0 = (accA.x + accB.x + accC.x + accD.x + dc * xc.x) * sc;
            m1 = (accA.y + accB.y + accC.y + accD.y + dc * xc.y) * sc;
            m2 = (accA.z + accB.z + accC.z + accD.z + dc * xc.z) * sc;
            m3 = (accA.w + accB.w + accC.w + accD.w + dc * xc.w) * sc;
        }
        int g   = r_loc >> 4;
        int w16 = r_loc & 15;
        int gd  = w16 & 7;
        int rh  = w16 >> 3;
#pragma unroll
        for (int p = 0; p < 2; p++) {
            int cp = 2 * lane + p;
            int q  = cp >> 3;
            int w8 = cp & 7;
            int tcc = w8 & 3;
            int kh  = w8 >> 2;
            int tw = (gd * 4 + tcc) * 4 + kh * 2 + rh;
            uint2 sm = (p == 0) ? split_bf2(m0, m1) : split_bf2(m2, m3);
            unsigned sxh = (p == 0) ? pack_bf2(xc.x, xc.y) : pack_bf2(xc.z, xc.w);
            stgbuf[stg_i(0, q, g, tw)] = sm.x;
            stgbuf[stg_i(1, q, g, tw)] = sm.y;
            stgbuf[stg_i(2, q, g, tw)] = sxh;
        }
    }
}

// ---------- persistent fused: weff-init + pipelined gather + 2 HMMA GEMMs + gate + LN ----------
__global__ void __launch_bounds__(FTHREADS, 1)
fused_kernel(const float* __restrict__ x,
             const float* __restrict__ msg_W, const float* __restrict__ msg_A,
             const float* __restrict__ msg_B,
             const float* __restrict__ gate_W, const float* __restrict__ gate_A,
             const float* __restrict__ gate_B,
             const float* __restrict__ msg_b, const float* __restrict__ gate_b,
             const float* __restrict__ ln_g, const float* __restrict__ ln_b,
             float* __restrict__ out) {
    extern __shared__ char smem[];
    unsigned* sB   = (unsigned*)smem;                  // B frags (3 images)
    unsigned* stg  = (unsigned*)(smem + SMB_STG);      // 2 staging sets
    float* s_mb = (float*)(smem + SMB_MB);
    float* s_gb = (float*)(smem + SMB_GB);
    float* s_ga = (float*)(smem + SMB_GA);
    float* s_be = (float*)(smem + SMB_BE);
    float* s1   = (float*)(smem + SMB_S1);             // [8][64]
    float* s2   = (float*)(smem + SMB_S2);

    int tid  = threadIdx.x;
    int w    = tid >> 5, lane = tid & 31;
    int cg   = w >> 1;            // col group (16 cols)
    int rg   = w & 1;             // row group (32 rows of the 64-row half)
    int gid  = lane >> 2;
    int tc4  = lane & 3;

    int2* ebuf = (int2*)(smem + SMB_EBUF) + w * BUFCAP;   // per-warp edge buffer

    // ---- init: compute effective-weight B-fragment images in-block ----
    {
        float* sA  = (float*)stg;          // msg_A [R*H] staged (staging area free now)
        float* sAg = sA + R * H;           // gate_A
        for (int i = tid; i < R * H; i += FTHREADS) {
            sA[i]  = msg_A[i];
            sAg[i] = gate_A[i];
        }
        if (tid < 128) {
            s_mb[tid] = msg_b[tid];
            s_gb[tid] = gate_b[tid];
            s_ga[tid] = ln_g[tid];
            s_be[tid] = ln_b[tid];
        }
        __syncthreads();

        int j = tid & 127;
        int kbase = (tid >> 7) * 32;
        float mB[R], gB[R];
#pragma unroll
        for (int r = 0; r < R; r += 4) {
            *(float4*)&mB[r] = *(const float4*)&msg_B[j * R + r];
            *(float4*)&gB[r] = *(const float4*)&gate_B[j * R + r];
        }
        unsigned short* img = (unsigned short*)sB;
        const int vstride = 8 * 16 * 32 * 4;
        int nt = j >> 3, n = j & 7;
#pragma unroll 1
        for (int kk = 0; kk < 32; kk++) {
            int k = kbase + kk;
            float am = 0.f, ag = 0.f;
#pragma unroll
            for (int r = 0; r < R; r++) {
                am += mB[r] * sA[r * H + k];
                ag += gB[r] * sAg[r * H + k];
            }
            float wm = msg_W[j * H + k] + SCALING * am;
            float wg = gate_W[j * H + k] + SCALING * ag;
            int q = k >> 4, k2 = k & 15;
            int T = n * 4 + ((k2 & 7) >> 1);
            int reg = k2 >> 3, half = k2 & 1;
            int idx = ((q * 16 + nt) * 32 + T) * 4 + reg * 2 + half;
            __nv_bfloat16 mh = __float2bfloat16(wm);
            __nv_bfloat16 ml = __float2bfloat16(wm - __bfloat162float(mh));
            __nv_bfloat16 gh = __float2bfloat16(wg);
            img[0 * vstride + idx] = *(unsigned short*)&mh;
            img[1 * vstride + idx] = *(unsigned short*)&ml;
            img[2 * vstride + idx] = *(unsigned short*)&gh;
        }
        __syncthreads();
    }

    const float4* x4 = (const float4*)x;

    int myTiles = (NT_TILES - 1 - blockIdx.x) / FGRID + 1;
    int nh = 2 * myTiles;

    // prologue: gather half 0
    {
        int base0 = blockIdx.x * TILE_M;
        gather_half(base0, stg, ebuf, x4, w, lane);
    }
    __syncthreads();

#pragma unroll 1
    for (int k = 0; k < nh; k++) {
        unsigned* cur = stg + (k & 1) * PLANE_W;
        unsigned* nxt = stg + ((k + 1) & 1) * PLANE_W;
        int tile = blockIdx.x + (k >> 1) * FGRID;
        int base = tile * TILE_M + (k & 1) * 64;

        // ---- pipelined gather of NEXT half (other staging set) ----
        if (k + 1 < nh) {
            int tile1 = blockIdx.x + ((k + 1) >> 1) * FGRID;
            int base1 = tile1 * TILE_M + ((k + 1) & 1) * 64;
            gather_half(base1, nxt, ebuf, x4, w, lane);
        }

        // ---- MMA: 64 x 128 x 128; msg 3-term split, gate pure bf16 ----
        float acc_m[2][2][4], acc_g[2][2][4];
#pragma unroll
        for (int mt = 0; mt < 2; mt++)
#pragma unroll
            for (int nt = 0; nt < 2; nt++)
#pragma unroll
                for (int d = 0; d < 4; d++) { acc_m[mt][nt][d] = 0.f; acc_g[mt][nt][d] = 0.f; }

#pragma unroll 1
        for (int q = 0; q < 8; q++) {
            uint4 afr[2][3];
#pragma unroll
            for (int mt = 0; mt < 2; mt++)
#pragma unroll
                for (int v = 0; v < 3; v++)
                    afr[mt][v] = *(const uint4*)&cur[stg_i(v, q, rg * 2 + mt, lane * 4)];
#pragma unroll
            for (int nt = 0; nt < 2; nt++) {
                int gnt = cg * 2 + nt;
                uint2 bmh = *(const uint2*)(sB + (((0 * 8 + q) * 16 + gnt) * 32 + lane) * 2);
                uint2 bml = *(const uint2*)(sB + (((1 * 8 + q) * 16 + gnt) * 32 + lane) * 2);
                uint2 bgh = *(const uint2*)(sB + (((2 * 8 + q) * 16 + gnt) * 32 + lane) * 2);
#pragma unroll
                for (int mt = 0; mt < 2; mt++) {
                    mma16816(acc_m[mt][nt], (const unsigned*)&afr[mt][0], (const unsigned*)&bmh);
                    mma16816(acc_m[mt][nt], (const unsigned*)&afr[mt][0], (const unsigned*)&bml);
                    mma16816(acc_m[mt][nt], (const unsigned*)&afr[mt][1], (const unsigned*)&bmh);
                    mma16816(acc_g[mt][nt], (const unsigned*)&afr[mt][2], (const unsigned*)&bgh);
                }
            }
        }

        // ---- epilogue: gate + residual, partial LN sums ----
        int rowbase = base + rg * 32;
        float sum1[2][2] = {{0.f, 0.f}, {0.f, 0.f}};   // [mt][rhh]
        float sum2[2][2] = {{0.f, 0.f}, {0.f, 0.f}};
#pragma unroll
        for (int mt = 0; mt < 2; mt++) {
            int r0 = rowbase + mt * 16 + gid;
            int r1 = r0 + 8;
#pragma unroll
            for (int nt = 0; nt < 2; nt++) {
                int c0 = cg * 16 + nt * 8 + 2 * tc4;
                float2 h0 = make_float2(0.f, 0.f), h1 = make_float2(0.f, 0.f);
                if (r0 < N_NODES) h0 = *(const float2*)(x + (size_t)r0 * H + c0);
                if (r1 < N_NODES) h1 = *(const float2*)(x + (size_t)r1 * H + c0);
                float mb0 = s_mb[c0], mb1 = s_mb[c0 + 1];
                float gb0 = s_gb[c0], gb1 = s_gb[c0 + 1];
                float* am = acc_m[mt][nt];
                float* ag = acc_g[mt][nt];
                float v0 = h0.x + (am[0] + mb0) / (1.f + __expf(-(ag[0] + gb0)));
                float v1 = h0.y + (am[1] + mb1) / (1.f + __expf(-(ag[1] + gb1)));
                float v2 = h1.x + (am[2] + mb0) / (1.f + __expf(-(ag[2] + gb0)));
                float v3 = h1.y + (am[3] + mb1) / (1.f + __expf(-(ag[3] + gb1)));
                am[0] = v0; am[1] = v1; am[2] = v2; am[3] = v3;
                sum1[mt][0] += v0 + v1;  sum2[mt][0] += v0 * v0 + v1 * v1;
                sum1[mt][1] += v2 + v3;  sum2[mt][1] += v2 * v2 + v3 * v3;
            }
        }
#pragma unroll
        for (int mt = 0; mt < 2; mt++)
#pragma unroll
            for (int rr = 0; rr < 2; rr++) {
                sum1[mt][rr] += __shfl_xor_sync(0xffffffffu, sum1[mt][rr], 1);
                sum1[mt][rr] += __shfl_xor_sync(0xffffffffu, sum1[mt][rr], 2);
                sum2[mt][rr] += __shfl_xor_sync(0xffffffffu, sum2[mt][rr], 1);
                sum2[mt][rr] += __shfl_xor_sync(0xffffffffu, sum2[mt][rr], 2);
            }
        if (tc4 == 0) {
#pragma unroll
            for (int mt = 0; mt < 2; mt++)
#pragma unroll
                for (int rr = 0; rr < 2; rr++) {
                    int rl = rg * 32 + mt * 16 + gid + rr * 8;
                    s1[cg * 64 + rl] = sum1[mt][rr];
                    s2[cg * 64 + rl] = sum2[mt][rr];
                }
        }
        __syncthreads();

        // ---- LN finalize + store ----
        float mu_[2][2], ri_[2][2];
#pragma unroll
        for (int mt = 0; mt < 2; mt++)
#pragma unroll
            for (int rr = 0; rr < 2; rr++) {
                int rl = rg * 32 + mt * 16 + gid + rr * 8;
                float S = 0.f, S2 = 0.f;
#pragma unroll
                for (int c = 0; c < 8; c++) { S += s1[c * 64 + rl]; S2 += s2[c * 64 + rl]; }
                float mu = S * (1.f / (float)H);
                float var = S2 * (1.f / (float)H) - mu * mu;
                mu_[mt][rr] = mu;
                ri_[mt][rr] = rsqrtf(var + LN_EPS);
            }
#pragma unroll
        for (int mt = 0; mt < 2; mt++) {
            int r0 = rowbase + mt * 16 + gid;
            int r1 = r0 + 8;
#pragma unroll
            for (int nt = 0; nt < 2; nt++) {
                int c0 = cg * 16 + nt * 8 + 2 * tc4;
                float ga0 = s_ga[c0], ga1 = s_ga[c0 + 1];
                float be0 = s_be[c0], be1 = s_be[c0 + 1];
                float* am = acc_m[mt][nt];
                if (r0 < N_NODES) {
                    float2 o;
                    o.x = (am[0] - mu_[mt][0]) * ri_[mt][0] * ga0 + be0;
                    o.y = (am[1] - mu_[mt][0]) * ri_[mt][0] * ga1 + be1;
                    *(float2*)(out + (size_t)r0 * H + c0) = o;
                }
                if (r1 < N_NODES) {
                    float2 o;
                    o.x = (am[2] - mu_[mt][1]) * ri_[mt][1] * ga0 + be0;
                    o.y = (am[3] - mu_[mt][1]) * ri_[mt][1] * ga1 + be1;
                    *(float2*)(out + (size_t)r1 * H + c0) = o;
                }
            }
        }
        __syncthreads();   // staging(next) complete + partials reuse safety
    }
}

// ---------- launch ----------
extern "C" void kernel_launch(void* const* d_in, const int* in_sizes, int n_in,
                              void* d_out, int out_size) {
    const float* x      = (const float*)d_in[0];
    const int*   ei     = (const int*)d_in[1];
    const float* msg_W  = (const float*)d_in[2];
    const float* msg_b  = (const float*)d_in[3];
    const float* msg_A  = (const float*)d_in[4];
    const float* msg_B  = (const float*)d_in[5];
    const float* gate_W = (const float*)d_in[6];
    const float* gate_b = (const float*)d_in[7];
    const float* gate_A = (const float*)d_in[8];
    const float* gate_B = (const float*)d_in[9];
    const float* ln_g   = (const float*)d_in[10];
    const float* ln_b   = (const float*)d_in[11];
    float* out = (float*)d_out;

    const int* rows = ei;
    const int* cols = ei + N_EDGES;

    hist_kernel<<<(N_EDGES + 255) / 256, 256>>>(cols);
    scan_pass1<<<SCAN_NB, SCAN_CHUNK>>>();
    scan_pass2<<<1, 256>>>();
    scan_pass3<<<SCAN_NB, SCAN_CHUNK>>>();
    scatter_kernel<<<(N_EDGES + 255) / 256, 256>>>(rows, cols);

    cudaFuncSetAttribute(fused_kernel, cudaFuncAttributeMaxDynamicSharedMemorySize, FUSED_SMEM);
    fused_kernel<<<FGRID, FTHREADS, FUSED_SMEM>>>(
        x, msg_W, msg_A, msg_B, gate_W, gate_A, gate_B,
        msg_b, gate_b, ln_g, ln_b, out);
}

// round 15
// speedup vs baseline: 1.1788x; 1.1788x over previous
#include <cuda_runtime.h>
#include <cuda_bf16.h>
#include <math.h>
#include <stdint.h>

#define N_NODES 100000
#define N_EDGES 600000
#define H 128
#define R 16
#define SCALING 2.0f
#define LN_EPS 1e-5f

#define SCAN_CHUNK 512
#define SCAN_NB ((N_NODES + SCAN_CHUNK - 1) / SCAN_CHUNK)   // 196

#define TILE_M 128
#define NT_TILES ((N_NODES + TILE_M - 1) / TILE_M)          // 782
#define FGRID 148
#define FTHREADS 512

#define QPAD 516                      // words per (v,q) staging plane (4*128 + 4 pad)
#define PLANE_W (3 * 8 * QPAD)        // words per staging set = 12384 (49536 B)
#define BUFCAP 128                    // edge records per warp buffer

// fused smem layout (bytes): 3 weight images + 2x staging sets + edge buffer
#define SMB_W    0                    // 3 x 32KB = 98304
#define SMB_STG  98304                // 2 x 49536 = 99072
#define SMB_MB   197376
#define SMB_GB   197888
#define SMB_GA   198400
#define SMB_BE   198912
#define SMB_S1   199424               // [8][64] f32
#define SMB_S2   201472
#define SMB_EBUF 203520               // 16 warps x 128 int2 = 16384
#define FUSED_SMEM 219904

// ---------- static device scratch ----------
__device__ int   g_deg[N_NODES];      // zero-init; scatter restores to zero each call
__device__ int   g_off[N_NODES + 1];
__device__ float g_dinv[N_NODES];
__device__ int2  g_erec[N_EDGES];     // packed (src, __float_as_int(dinv[src]))
__device__ int   g_bsum[256];
// B fragments: [v 3][q 8][nt 16][T 32][b0,b1] u32 = 96 KB (msg_hi, msg_lo, gate_hi)
__device__ unsigned g_wfrag[3 * 8 * 16 * 32 * 2];

// ---------- helpers ----------
__device__ __forceinline__ unsigned pack_bf2(float e0, float e1) {
    unsigned r;
    asm("cvt.rn.bf16x2.f32 %0, %1, %2;" : "=r"(r) : "f"(e1), "f"(e0));  // lo=e0, hi=e1
    return r;
}
__device__ __forceinline__ uint2 split_bf2(float e0, float e1) {
    unsigned hi = pack_bf2(e0, e1);
    float h0 = __uint_as_float(hi << 16);
    float h1 = __uint_as_float(hi & 0xffff0000u);
    unsigned lo = pack_bf2(e0 - h0, e1 - h1);
    return make_uint2(hi, lo);
}
__device__ __forceinline__ void mma16816(float* d, const unsigned* a, const unsigned* b) {
    asm volatile(
        "mma.sync.aligned.m16n8k16.row.col.f32.bf16.bf16.f32 "
        "{%0,%1,%2,%3}, {%4,%5,%6,%7}, {%8,%9}, {%0,%1,%2,%3};"
        : "+f"(d[0]), "+f"(d[1]), "+f"(d[2]), "+f"(d[3])
        : "r"(a[0]), "r"(a[1]), "r"(a[2]), "r"(a[3]), "r"(b[0]), "r"(b[1]));
}
__device__ __forceinline__ int stg_i(int v, int q, int g, int tw) {
    return (v * 8 + q) * QPAD + g * 128 + tw;
}

// ---------- 1. in-degree histogram ----------
__global__ void hist_kernel(const int* __restrict__ col) {
    int e = blockIdx.x * blockDim.x + threadIdx.x;
    if (e < N_EDGES) atomicAdd(&g_deg[col[e]], 1);
}

// ---------- 2. parallel 3-pass scan (coalesced) ----------
__global__ void scan_pass1() {
    __shared__ int sh[SCAN_CHUNK];
    int i = blockIdx.x * SCAN_CHUNK + threadIdx.x;
    sh[threadIdx.x] = (i < N_NODES) ? g_deg[i] : 0;
    __syncthreads();
    for (int off = SCAN_CHUNK / 2; off > 0; off >>= 1) {
        if (threadIdx.x < off) sh[threadIdx.x] += sh[threadIdx.x + off];
        __syncthreads();
    }
    if (threadIdx.x == 0) g_bsum[blockIdx.x] = sh[0];
}
__global__ void scan_pass2() {       // shfl two-level scan over 196 block sums
    __shared__ int wsum[8];
    int t = threadIdx.x;             // 256 threads = 8 warps
    int lane = t & 31, wid = t >> 5;
    int v = (t < SCAN_NB) ? g_bsum[t] : 0;
    int s = v;
#pragma unroll
    for (int off = 1; off < 32; off <<= 1) {
        int n = __shfl_up_sync(0xffffffffu, s, off);
        if (lane >= off) s += n;
    }
    if (lane == 31) wsum[wid] = s;
    __syncthreads();
    if (wid == 0) {
        int ws = (lane < 8) ? wsum[lane] : 0;
#pragma unroll
        for (int off = 1; off < 8; off <<= 1) {
            int n = __shfl_up_sync(0xffffffffu, ws, off);
            if (lane >= off) ws += n;
        }
        if (lane < 8) wsum[lane] = ws;
    }
    __syncthreads();
    int pre = s - v + (wid > 0 ? wsum[wid - 1] : 0);   // exclusive prefix
    if (t < SCAN_NB) g_bsum[t] = pre;
    if (t == 255) g_off[N_NODES] = pre + v;
}
__global__ void scan_pass3() {       // + dinv folded in
    __shared__ int sh[SCAN_CHUNK];
    int i = blockIdx.x * SCAN_CHUNK + threadIdx.x;
    int v = (i < N_NODES) ? g_deg[i] : 0;
    sh[threadIdx.x] = v;
    __syncthreads();
    for (int off = 1; off < SCAN_CHUNK; off <<= 1) {
        int t = (threadIdx.x >= off) ? sh[threadIdx.x - off] : 0;
        __syncthreads();
        sh[threadIdx.x] += t;
        __syncthreads();
    }
    if (i < N_NODES) {
        g_off[i]  = g_bsum[blockIdx.x] + sh[threadIdx.x] - v;
        g_dinv[i] = rsqrtf((float)(v + 1));
    }
}

// ---------- 3. bucket edges by target; records (src, dinv[src]); zeroes g_deg ----------
__global__ void scatter_kernel(const int* __restrict__ row, const int* __restrict__ col) {
    int e = blockIdx.x * blockDim.x + threadIdx.x;
    if (e < N_EDGES) {
        int c = col[e];
        int r = row[e];
        int p = atomicAdd(&g_deg[c], -1) - 1;    // restores g_deg to 0
        g_erec[g_off[c] + p] = make_int2(r, __float_as_int(g_dinv[r]));
    }
}

// ---------- 0. effective weights -> B-fragment images (msg hi/lo, gate hi) ----------
__global__ void weff_kernel(const float* __restrict__ msg_W, const float* __restrict__ msg_A,
                            const float* __restrict__ msg_B,
                            const float* __restrict__ gate_W, const float* __restrict__ gate_A,
                            const float* __restrict__ gate_B) {
    int k = blockIdx.x;          // input feature 0..127
    int j = threadIdx.x;         // output feature 0..127
    __shared__ float sam[R], sag[R];
    if (j < R) { sam[j] = msg_A[j * H + k]; sag[j] = gate_A[j * H + k]; }
    __syncthreads();
    float am = 0.f, ag = 0.f;
#pragma unroll
    for (int r = 0; r < R; r++) {
        am += msg_B[j * R + r] * sam[r];
        ag += gate_B[j * R + r] * sag[r];
    }
    float wm = msg_W[j * H + k] + SCALING * am;
    float wg = gate_W[j * H + k] + SCALING * ag;

    int q  = k >> 4, k2 = k & 15;
    int nt = j >> 3, n  = j & 7;
    int T  = n * 4 + ((k2 & 7) >> 1);
    int reg = k2 >> 3, half = k2 & 1;
    int idx = ((q * 16 + nt) * 32 + T) * 4 + reg * 2 + half;  // u16 within variant
    int vstride = 8 * 16 * 32 * 4;

    unsigned short* img = (unsigned short*)g_wfrag;
    __nv_bfloat16 mh = __float2bfloat16(wm);
    __nv_bfloat16 ml = __float2bfloat16(wm - __bfloat162float(mh));
    __nv_bfloat16 gh = __float2bfloat16(wg);
    img[0 * vstride + idx] = *(unsigned short*)&mh;
    img[1 * vstride + idx] = *(unsigned short*)&ml;
    img[2 * vstride + idx] = *(unsigned short*)&gh;
}

// ---------- gather one 64-row half into a staging set ----------
__device__ __forceinline__ void gather_half(
    int base, unsigned* stgbuf, int2* ebuf,
    const float4* __restrict__ x4, int w, int lane)
{
    int n0  = base + w * 4;
    int n0c = (n0     < N_NODES) ? n0     : N_NODES;
    int n4c = (n0 + 4 < N_NODES) ? n0 + 4 : N_NODES;
    int begAll = g_off[n0c];
    int endAll = g_off[n4c];
    int cnt    = endAll - begAll;
    bool fast  = (cnt <= BUFCAP);
    __syncwarp();                       // WAR: prior reads of ebuf done
    if (fast) {
#pragma unroll 1
        for (int cb = 0; cb < cnt; cb += 32)
            if (cb + lane < cnt) ebuf[cb + lane] = g_erec[begAll + cb + lane];
        __syncwarp();
    }
#pragma unroll 1
    for (int i = 0; i < 4; i++) {
        int r_loc = w * 4 + i;
        int node  = base + r_loc;
        float4 xc = make_float4(0.f, 0.f, 0.f, 0.f);
        float m0 = 0.f, m1 = 0.f, m2 = 0.f, m3 = 0.f;
        if (node < N_NODES) {
            float4 accA = make_float4(0.f, 0.f, 0.f, 0.f);
            float4 accB = make_float4(0.f, 0.f, 0.f, 0.f);
            float4 accC = make_float4(0.f, 0.f, 0.f, 0.f);
            float4 accD = make_float4(0.f, 0.f, 0.f, 0.f);
            int beg = g_off[node], end = g_off[node + 1];
            if (fast) {
                int jb = beg - begAll, je = end - begAll;
#pragma unroll 1
                for (int j = jb; j < je; j += 4) {
                    int2 rA = ebuf[j];
                    int2 rB = (j + 1 < je) ? ebuf[j + 1] : make_int2(0, 0);
                    int2 rC = (j + 2 < je) ? ebuf[j + 2] : make_int2(0, 0);
                    int2 rD = (j + 3 < je) ? ebuf[j + 3] : make_int2(0, 0);
                    float4 vA = x4[rA.x * 32 + lane];
                    float4 vB = x4[rB.x * 32 + lane];
                    float4 vC = x4[rC.x * 32 + lane];
                    float4 vD = x4[rD.x * 32 + lane];
                    float wA = __int_as_float(rA.y), wB = __int_as_float(rB.y);
                    float wC = __int_as_float(rC.y), wD = __int_as_float(rD.y);
                    accA.x += wA * vA.x; accA.y += wA * vA.y; accA.z += wA * vA.z; accA.w += wA * vA.w;
                    accB.x += wB * vB.x; accB.y += wB * vB.y; accB.z += wB * vB.z; accB.w += wB * vB.w;
                    accC.x += wC * vC.x; accC.y += wC * vC.y; accC.z += wC * vC.z; accC.w += wC * vC.w;
                    accD.x += wD * vD.x; accD.y += wD * vD.y; accD.z += wD * vD.z; accD.w += wD * vD.w;
                }
            } else {
#pragma unroll 1
                for (int e = beg; e < end; e += 2) {
                    int2 rA = g_erec[e];
                    int2 rB = (e + 1 < end) ? g_erec[e + 1] : make_int2(0, 0);
                    float4 vA = x4[rA.x * 32 + lane];
                    float4 vB = x4[rB.x * 32 + lane];
                    float wA = __int_as_float(rA.y), wB = __int_as_float(rB.y);
                    accA.x += wA * vA.x; accA.y += wA * vA.y; accA.z += wA * vA.z; accA.w += wA * vA.w;
                    accB.x += wB * vB.x; accB.y += wB * vB.y; accB.z += wB * vB.z; accB.w += wB * vB.w;
                }
            }
            float dc = g_dinv[node];
            float sc = dc / (float)(end - beg + 1);
            xc = x4[node * 32 + lane];
            m0 = (accA.x + accB.x + accC.x + accD.x + dc * xc.x) * sc;
            m1 = (accA.y + accB.y + accC.y + accD.y + dc * xc.y) * sc;
            m2 = (accA.z + accB.z + accC.z + accD.z + dc * xc.z) * sc;
            m3 = (accA.w + accB.w + accC.w + accD.w + dc * xc.w) * sc;
        }
        int g   = r_loc >> 4;
        int w16 = r_loc & 15;
        int gd  = w16 & 7;
        int rh  = w16 >> 3;
#pragma unroll
        for (int p = 0; p < 2; p++) {
            int cp = 2 * lane + p;
            int q  = cp >> 3;
            int w8 = cp & 7;
            int tcc = w8 & 3;
            int kh  = w8 >> 2;
            int tw = (gd * 4 + tcc) * 4 + kh * 2 + rh;
            uint2 sm = (p == 0) ? split_bf2(m0, m1) : split_bf2(m2, m3);
            unsigned sxh = (p == 0) ? pack_bf2(xc.x, xc.y) : pack_bf2(xc.z, xc.w);
            stgbuf[stg_i(0, q, g, tw)] = sm.x;
            stgbuf[stg_i(1, q, g, tw)] = sm.y;
            stgbuf[stg_i(2, q, g, tw)] = sxh;
        }
    }
}

// ---------- persistent fused: pipelined gather + 2 HMMA GEMMs + gate + LN ----------
__global__ void __launch_bounds__(FTHREADS, 1)
fused_kernel(const float* __restrict__ x,
             const float* __restrict__ msg_b, const float* __restrict__ gate_b,
             const float* __restrict__ ln_g, const float* __restrict__ ln_b,
             float* __restrict__ out) {
    extern __shared__ char smem[];
    unsigned* sB   = (unsigned*)smem;                  // B frags (3 images)
    unsigned* stg  = (unsigned*)(smem + SMB_STG);      // 2 staging sets
    float* s_mb = (float*)(smem + SMB_MB);
    float* s_gb = (float*)(smem + SMB_GB);
    float* s_ga = (float*)(smem + SMB_GA);
    float* s_be = (float*)(smem + SMB_BE);
    float* s1   = (float*)(smem + SMB_S1);             // [8][64]
    float* s2   = (float*)(smem + SMB_S2);

    int tid  = threadIdx.x;
    int w    = tid >> 5, lane = tid & 31;
    int cg   = w >> 1;            // col group (16 cols)
    int rg   = w & 1;             // row group (32 rows of the 64-row half)
    int gid  = lane >> 2;
    int tc4  = lane & 3;

    int2* ebuf = (int2*)(smem + SMB_EBUF) + w * BUFCAP;   // per-warp edge buffer

    // load B images + biases (once)
    {
        const uint4* src = (const uint4*)g_wfrag;
        uint4* dst = (uint4*)sB;
#pragma unroll
        for (int i = 0; i < 12; i++) dst[tid + i * FTHREADS] = src[tid + i * FTHREADS];
        if (tid < 128) {
            s_mb[tid] = msg_b[tid];
            s_gb[tid] = gate_b[tid];
            s_ga[tid] = ln_g[tid];
            s_be[tid] = ln_b[tid];
        }
    }

    const float4* x4 = (const float4*)x;

    int myTiles = (NT_TILES - 1 - blockIdx.x) / FGRID + 1;
    int nh = 2 * myTiles;

    // prologue: gather half 0
    {
        int base0 = blockIdx.x * TILE_M;
        gather_half(base0, stg, ebuf, x4, w, lane);
    }
    __syncthreads();

#pragma unroll 1
    for (int k = 0; k < nh; k++) {
        unsigned* cur = stg + (k & 1) * PLANE_W;
        unsigned* nxt = stg + ((k + 1) & 1) * PLANE_W;
        int tile = blockIdx.x + (k >> 1) * FGRID;
        int base = tile * TILE_M + (k & 1) * 64;

        // ---- pipelined gather of NEXT half (other staging set) ----
        if (k + 1 < nh) {
            int tile1 = blockIdx.x + ((k + 1) >> 1) * FGRID;
            int base1 = tile1 * TILE_M + ((k + 1) & 1) * 64;
            gather_half(base1, nxt, ebuf, x4, w, lane);
        }

        // ---- MMA: 64 x 128 x 128; msg 3-term split, gate pure bf16 ----
        float acc_m[2][2][4], acc_g[2][2][4];
#pragma unroll
        for (int mt = 0; mt < 2; mt++)
#pragma unroll
            for (int nt = 0; nt < 2; nt++)
#pragma unroll
                for (int d = 0; d < 4; d++) { acc_m[mt][nt][d] = 0.f; acc_g[mt][nt][d] = 0.f; }

#pragma unroll 1
        for (int q = 0; q < 8; q++) {
            uint4 afr[2][3];
#pragma unroll
            for (int mt = 0; mt < 2; mt++)
#pragma unroll
                for (int v = 0; v < 3; v++)
                    afr[mt][v] = *(const uint4*)&cur[stg_i(v, q, rg * 2 + mt, lane * 4)];
#pragma unroll
            for (int nt = 0; nt < 2; nt++) {
                int gnt = cg * 2 + nt;
                uint2 bmh = *(const uint2*)(sB + (((0 * 8 + q) * 16 + gnt) * 32 + lane) * 2);
                uint2 bml = *(const uint2*)(sB + (((1 * 8 + q) * 16 + gnt) * 32 + lane) * 2);
                uint2 bgh = *(const uint2*)(sB + (((2 * 8 + q) * 16 + gnt) * 32 + lane) * 2);
#pragma unroll
                for (int mt = 0; mt < 2; mt++) {
                    mma16816(acc_m[mt][nt], (const unsigned*)&afr[mt][0], (const unsigned*)&bmh);
                    mma16816(acc_m[mt][nt], (const unsigned*)&afr[mt][0], (const unsigned*)&bml);
                    mma16816(acc_m[mt][nt], (const unsigned*)&afr[mt][1], (const unsigned*)&bmh);
                    mma16816(acc_g[mt][nt], (const unsigned*)&afr[mt][2], (const unsigned*)&bgh);
                }
            }
        }

        // ---- epilogue: gate + residual, partial LN sums ----
        int rowbase = base + rg * 32;
        float sum1[2][2] = {{0.f, 0.f}, {0.f, 0.f}};   // [mt][rhh]
        float sum2[2][2] = {{0.f, 0.f}, {0.f, 0.f}};
#pragma unroll
        for (int mt = 0; mt < 2; mt++) {
            int r0 = rowbase + mt * 16 + gid;
            int r1 = r0 + 8;
#pragma unroll
            for (int nt = 0; nt < 2; nt++) {
                int c0 = cg * 16 + nt * 8 + 2 * tc4;
                float2 h0 = make_float2(0.f, 0.f), h1 = make_float2(0.f, 0.f);
                if (r0 < N_NODES) h0 = *(const float2*)(x + (size_t)r0 * H + c0);
                if (r1 < N_NODES) h1 = *(const float2*)(x + (size_t)r1 * H + c0);
                float mb0 = s_mb[c0], mb1 = s_mb[c0 + 1];
                float gb0 = s_gb[c0], gb1 = s_gb[c0 + 1];
                float* am = acc_m[mt][nt];
                float* ag = acc_g[mt][nt];
                float v0 = h0.x + (am[0] + mb0) / (1.f + __expf(-(ag[0] + gb0)));
                float v1 = h0.y + (am[1] + mb1) / (1.f + __expf(-(ag[1] + gb1)));
                float v2 = h1.x + (am[2] + mb0) / (1.f + __expf(-(ag[2] + gb0)));
                float v3 = h1.y + (am[3] + mb1) / (1.f + __expf(-(ag[3] + gb1)));
                am[0] = v0; am[1] = v1; am[2] = v2; am[3] = v3;
                sum1[mt][0] += v0 + v1;  sum2[mt][0] += v0 * v0 + v1 * v1;
                sum1[mt][1] += v2 + v3;  sum2[mt][1] += v2 * v2 + v3 * v3;
            }
        }
#pragma unroll
        for (int mt = 0; mt < 2; mt++)
#pragma unroll
            for (int rr = 0; rr < 2; rr++) {
                sum1[mt][rr] += __shfl_xor_sync(0xffffffffu, sum1[mt][rr], 1);
                sum1[mt][rr] += __shfl_xor_sync(0xffffffffu, sum1[mt][rr], 2);
                sum2[mt][rr] += __shfl_xor_sync(0xffffffffu, sum2[mt][rr], 1);
                sum2[mt][rr] += __shfl_xor_sync(0xffffffffu, sum2[mt][rr], 2);
            }
        if (tc4 == 0) {
#pragma unroll
            for (int mt = 0; mt < 2; mt++)
#pragma unroll
                for (int rr = 0; rr < 2; rr++) {
                    int rl = rg * 32 + mt * 16 + gid + rr * 8;
                    s1[cg * 64 + rl] = sum1[mt][rr];
                    s2[cg * 64 + rl] = sum2[mt][rr];
                }
        }
        __syncthreads();

        // ---- LN finalize + store ----
        float mu_[2][2], ri_[2][2];
#pragma unroll
        for (int mt = 0; mt < 2; mt++)
#pragma unroll
            for (int rr = 0; rr < 2; rr++) {
                int rl = rg * 32 + mt * 16 + gid + rr * 8;
                float S = 0.f, S2 = 0.f;
#pragma unroll
                for (int c = 0; c < 8; c++) { S += s1[c * 64 + rl]; S2 += s2[c * 64 + rl]; }
                float mu = S * (1.f / (float)H);
                float var = S2 * (1.f / (float)H) - mu * mu;
                mu_[mt][rr] = mu;
                ri_[mt][rr] = rsqrtf(var + LN_EPS);
            }
#pragma unroll
        for (int mt = 0; mt < 2; mt++) {
            int r0 = rowbase + mt * 16 + gid;
            int r1 = r0 + 8;
#pragma unroll
            for (int nt = 0; nt < 2; nt++) {
                int c0 = cg * 16 + nt * 8 + 2 * tc4;
                float ga0 = s_ga[c0], ga1 = s_ga[c0 + 1];
                float be0 = s_be[c0], be1 = s_be[c0 + 1];
                float* am = acc_m[mt][nt];
                if (r0 < N_NODES) {
                    float2 o;
                    o.x = (am[0] - mu_[mt][0]) * ri_[mt][0] * ga0 + be0;
                    o.y = (am[1] - mu_[mt][0]) * ri_[mt][0] * ga1 + be1;
                    *(float2*)(out + (size_t)r0 * H + c0) = o;
                }
                if (r1 < N_NODES) {
                    float2 o;
                    o.x = (am[2] - mu_[mt][1]) * ri_[mt][1] * ga0 + be0;
                    o.y = (am[3] - mu_[mt][1]) * ri_[mt][1] * ga1 + be1;
                    *(float2*)(out + (size_t)r1 * H + c0) = o;
                }
            }
        }
        __syncthreads();   // staging(next) complete + partials reuse safety
    }
}

// ---------- launch ----------
extern "C" void kernel_launch(void* const* d_in, const int* in_sizes, int n_in,
                              void* d_out, int out_size) {
    const float* x      = (const float*)d_in[0];
    const int*   ei     = (const int*)d_in[1];
    const float* msg_W  = (const float*)d_in[2];
    const float* msg_b  = (const float*)d_in[3];
    const float* msg_A  = (const float*)d_in[4];
    const float* msg_B  = (const float*)d_in[5];
    const float* gate_W = (const float*)d_in[6];
    const float* gate_b = (const float*)d_in[7];
    const float* gate_A = (const float*)d_in[8];
    const float* gate_B = (const float*)d_in[9];
    const float* ln_g   = (const float*)d_in[10];
    const float* ln_b   = (const float*)d_in[11];
    float* out = (float*)d_out;

    const int* rows = ei;
    const int* cols = ei + N_EDGES;

    weff_kernel<<<H, H>>>(msg_W, msg_A, msg_B, gate_W, gate_A, gate_B);
    hist_kernel<<<(N_EDGES + 255) / 256, 256>>>(cols);
    scan_pass1<<<SCAN_NB, SCAN_CHUNK>>>();
    scan_pass2<<<1, 256>>>();
    scan_pass3<<<SCAN_NB, SCAN_CHUNK>>>();
    scatter_kernel<<<(N_EDGES + 255) / 256, 256>>>(rows, cols);

    cudaFuncSetAttribute(fused_kernel, cudaFuncAttributeMaxDynamicSharedMemorySize, FUSED_SMEM);
    fused_kernel<<<FGRID, FTHREADS, FUSED_SMEM>>>(x, msg_b, gate_b, ln_g, ln_b, out);
}

// round 16
// speedup vs baseline: 1.2322x; 1.0453x over previous
#include <cuda_runtime.h>
#include <cuda_bf16.h>
#include <math.h>
#include <stdint.h>

#define N_NODES 100000
#define N_EDGES 600000
#define H 128
#define R 16
#define SCALING 2.0f
#define LN_EPS 1e-5f

#define SCAN_CHUNK 512
#define SCAN_NB ((N_NODES + SCAN_CHUNK - 1) / SCAN_CHUNK)   // 196

#define TILE_M 128
#define NT_TILES ((N_NODES + TILE_M - 1) / TILE_M)          // 782
#define FGRID 148
#define FTHREADS 512

#define QPAD 516                      // words per (v,q) staging plane (4*128 + 4 pad)
#define PLANE_W (3 * 8 * QPAD)        // words per staging set = 12384 (49536 B)
#define BUFCAP 128                    // edge records per warp buffer

// fused smem layout (bytes): 3 weight images + 2x staging sets + edge buffer
#define SMB_W    0                    // 3 x 32KB = 98304
#define SMB_STG  98304                // 2 x 49536 = 99072
#define SMB_MB   197376
#define SMB_GB   197888
#define SMB_GA   198400
#define SMB_BE   198912
#define SMB_S1   199424               // [8][64] f32
#define SMB_S2   201472
#define SMB_EBUF 203520               // 16 warps x 128 int2 = 16384
#define FUSED_SMEM 219904

// ---------- static device scratch ----------
__device__ int   g_deg[N_NODES];      // zero-init; scatter restores to zero each call
__device__ int   g_off[N_NODES + 1];
__device__ float g_dinv[N_NODES];
__device__ int2  g_erec[N_EDGES];     // packed (src, __float_as_int(dinv[src]))
__device__ int   g_bsum[256];
// B fragments: [v 3][q 8][nt 16][T 32][b0,b1] u32 = 96 KB (msg_hi, msg_lo, gate_hi)
__device__ unsigned g_wfrag[3 * 8 * 16 * 32 * 2];

// ---------- helpers ----------
__device__ __forceinline__ unsigned pack_bf2(float e0, float e1) {
    unsigned r;
    asm("cvt.rn.bf16x2.f32 %0, %1, %2;" : "=r"(r) : "f"(e1), "f"(e0));  // lo=e0, hi=e1
    return r;
}
__device__ __forceinline__ uint2 split_bf2(float e0, float e1) {
    unsigned hi = pack_bf2(e0, e1);
    float h0 = __uint_as_float(hi << 16);
    float h1 = __uint_as_float(hi & 0xffff0000u);
    unsigned lo = pack_bf2(e0 - h0, e1 - h1);
    return make_uint2(hi, lo);
}
__device__ __forceinline__ void mma16816(float* d, const unsigned* a, const unsigned* b) {
    asm volatile(
        "mma.sync.aligned.m16n8k16.row.col.f32.bf16.bf16.f32 "
        "{%0,%1,%2,%3}, {%4,%5,%6,%7}, {%8,%9}, {%0,%1,%2,%3};"
        : "+f"(d[0]), "+f"(d[1]), "+f"(d[2]), "+f"(d[3])
        : "r"(a[0]), "r"(a[1]), "r"(a[2]), "r"(a[3]), "r"(b[0]), "r"(b[1]));
}
__device__ __forceinline__ int stg_i(int v, int q, int g, int tw) {
    return (v * 8 + q) * QPAD + g * 128 + tw;
}

// ---------- 1. in-degree histogram ----------
__global__ void hist_kernel(const int* __restrict__ col) {
    int e = blockIdx.x * blockDim.x + threadIdx.x;
    if (e < N_EDGES) atomicAdd(&g_deg[col[e]], 1);
}

// ---------- 2. parallel 3-pass scan (coalesced) ----------
__global__ void scan_pass1() {
    __shared__ int sh[SCAN_CHUNK];
    int i = blockIdx.x * SCAN_CHUNK + threadIdx.x;
    sh[threadIdx.x] = (i < N_NODES) ? g_deg[i] : 0;
    __syncthreads();
    for (int off = SCAN_CHUNK / 2; off > 0; off >>= 1) {
        if (threadIdx.x < off) sh[threadIdx.x] += sh[threadIdx.x + off];
        __syncthreads();
    }
    if (threadIdx.x == 0) g_bsum[blockIdx.x] = sh[0];
}
__global__ void scan_pass2() {       // shfl two-level scan over 196 block sums
    __shared__ int wsum[8];
    int t = threadIdx.x;             // 256 threads = 8 warps
    int lane = t & 31, wid = t >> 5;
    int v = (t < SCAN_NB) ? g_bsum[t] : 0;
    int s = v;
#pragma unroll
    for (int off = 1; off < 32; off <<= 1) {
        int n = __shfl_up_sync(0xffffffffu, s, off);
        if (lane >= off) s += n;
    }
    if (lane == 31) wsum[wid] = s;
    __syncthreads();
    if (wid == 0) {
        int ws = (lane < 8) ? wsum[lane] : 0;
#pragma unroll
        for (int off = 1; off < 8; off <<= 1) {
            int n = __shfl_up_sync(0xffffffffu, ws, off);
            if (lane >= off) ws += n;
        }
        if (lane < 8) wsum[lane] = ws;
    }
    __syncthreads();
    int pre = s - v + (wid > 0 ? wsum[wid - 1] : 0);   // exclusive prefix
    if (t < SCAN_NB) g_bsum[t] = pre;
    if (t == 255) g_off[N_NODES] = pre + v;
}
__global__ void scan_pass3() {       // + dinv folded in
    __shared__ int sh[SCAN_CHUNK];
    int i = blockIdx.x * SCAN_CHUNK + threadIdx.x;
    int v = (i < N_NODES) ? g_deg[i] : 0;
    sh[threadIdx.x] = v;
    __syncthreads();
    for (int off = 1; off < SCAN_CHUNK; off <<= 1) {
        int t = (threadIdx.x >= off) ? sh[threadIdx.x - off] : 0;
        __syncthreads();
        sh[threadIdx.x] += t;
        __syncthreads();
    }
    if (i < N_NODES) {
        g_off[i]  = g_bsum[blockIdx.x] + sh[threadIdx.x] - v;
        g_dinv[i] = rsqrtf((float)(v + 1));
    }
}

// ---------- 3. bucket edges by target; records (src, dinv[src]); zeroes g_deg ----------
__global__ void scatter_kernel(const int* __restrict__ row, const int* __restrict__ col) {
    int e = blockIdx.x * blockDim.x + threadIdx.x;
    if (e < N_EDGES) {
        int c = col[e];
        int r = row[e];
        int p = atomicAdd(&g_deg[c], -1) - 1;    // restores g_deg to 0
        g_erec[g_off[c] + p] = make_int2(r, __float_as_int(g_dinv[r]));
    }
}

// ---------- 0. effective weights -> B-fragment images (msg hi/lo, gate hi) ----------
__global__ void weff_kernel(const float* __restrict__ msg_W, const float* __restrict__ msg_A,
                            const float* __restrict__ msg_B,
                            const float* __restrict__ gate_W, const float* __restrict__ gate_A,
                            const float* __restrict__ gate_B) {
    int k = blockIdx.x;          // input feature 0..127
    int j = threadIdx.x;         // output feature 0..127
    __shared__ float sam[R], sag[R];
    if (j < R) { sam[j] = msg_A[j * H + k]; sag[j] = gate_A[j * H + k]; }
    __syncthreads();
    float am = 0.f, ag = 0.f;
#pragma unroll
    for (int r = 0; r < R; r++) {
        am += msg_B[j * R + r] * sam[r];
        ag += gate_B[j * R + r] * sag[r];
    }
    float wm = msg_W[j * H + k] + SCALING * am;
    float wg = gate_W[j * H + k] + SCALING * ag;

    int q  = k >> 4, k2 = k & 15;
    int nt = j >> 3, n  = j & 7;
    int T  = n * 4 + ((k2 & 7) >> 1);
    int reg = k2 >> 3, half = k2 & 1;
    int idx = ((q * 16 + nt) * 32 + T) * 4 + reg * 2 + half;  // u16 within variant
    int vstride = 8 * 16 * 32 * 4;

    unsigned short* img = (unsigned short*)g_wfrag;
    __nv_bfloat16 mh = __float2bfloat16(wm);
    __nv_bfloat16 ml = __float2bfloat16(wm - __bfloat162float(mh));
    __nv_bfloat16 gh = __float2bfloat16(wg);
    img[0 * vstride + idx] = *(unsigned short*)&mh;
    img[1 * vstride + idx] = *(unsigned short*)&ml;
    img[2 * vstride + idx] = *(unsigned short*)&gh;
}

// ---------- gather one 64-row half into a staging set ----------
__device__ __forceinline__ void gather_half(
    int base, unsigned* stgbuf, int2* ebuf,
    const float4* __restrict__ x4, int w, int lane)
{
    int n0  = base + w * 4;
    int n0c = (n0     < N_NODES) ? n0     : N_NODES;
    int n4c = (n0 + 4 < N_NODES) ? n0 + 4 : N_NODES;
    int begAll = g_off[n0c];
    int endAll = g_off[n4c];
    int cnt    = endAll - begAll;
    bool fast  = (cnt <= BUFCAP);
    __syncwarp();                       // WAR: prior reads of ebuf done
    if (fast) {
#pragma unroll 1
        for (int cb = 0; cb < cnt; cb += 32)
            if (cb + lane < cnt) ebuf[cb + lane] = g_erec[begAll + cb + lane];
        __syncwarp();
    }
#pragma unroll 1
    for (int i = 0; i < 4; i++) {
        int r_loc = w * 4 + i;
        int node  = base + r_loc;
        float4 xc = make_float4(0.f, 0.f, 0.f, 0.f);
        float m0 = 0.f, m1 = 0.f, m2 = 0.f, m3 = 0.f;
        if (node < N_NODES) {
            float4 accA = make_float4(0.f, 0.f, 0.f, 0.f);
            float4 accB = make_float4(0.f, 0.f, 0.f, 0.f);
            float4 accC = make_float4(0.f, 0.f, 0.f, 0.f);
            float4 accD = make_float4(0.f, 0.f, 0.f, 0.f);
            int beg = g_off[node], end = g_off[node + 1];
            if (fast) {
                int jb = beg - begAll, je = end - begAll;
#pragma unroll 2
                for (int j = jb; j < je; j += 4) {
                    int2 rA = ebuf[j];
                    int2 rB = (j + 1 < je) ? ebuf[j + 1] : make_int2(0, 0);
                    int2 rC = (j + 2 < je) ? ebuf[j + 2] : make_int2(0, 0);
                    int2 rD = (j + 3 < je) ? ebuf[j + 3] : make_int2(0, 0);
                    float4 vA = x4[rA.x * 32 + lane];
                    float4 vB = x4[rB.x * 32 + lane];
                    float4 vC = x4[rC.x * 32 + lane];
                    float4 vD = x4[rD.x * 32 + lane];
                    float wA = __int_as_float(rA.y), wB = __int_as_float(rB.y);
                    float wC = __int_as_float(rC.y), wD = __int_as_float(rD.y);
                    accA.x += wA * vA.x; accA.y += wA * vA.y; accA.z += wA * vA.z; accA.w += wA * vA.w;
                    accB.x += wB * vB.x; accB.y += wB * vB.y; accB.z += wB * vB.z; accB.w += wB * vB.w;
                    accC.x += wC * vC.x; accC.y += wC * vC.y; accC.z += wC * vC.z; accC.w += wC * vC.w;
                    accD.x += wD * vD.x; accD.y += wD * vD.y; accD.z += wD * vD.z; accD.w += wD * vD.w;
                }
            } else {
#pragma unroll 1
                for (int e = beg; e < end; e += 2) {
                    int2 rA = g_erec[e];
                    int2 rB = (e + 1 < end) ? g_erec[e + 1] : make_int2(0, 0);
                    float4 vA = x4[rA.x * 32 + lane];
                    float4 vB = x4[rB.x * 32 + lane];
                    float wA = __int_as_float(rA.y), wB = __int_as_float(rB.y);
                    accA.x += wA * vA.x; accA.y += wA * vA.y; accA.z += wA * vA.z; accA.w += wA * vA.w;
                    accB.x += wB * vB.x; accB.y += wB * vB.y; accB.z += wB * vB.z; accB.w += wB * vB.w;
                }
            }
            float dc = g_dinv[node];
            float sc = dc / (float)(end - beg + 1);
            xc = x4[node * 32 + lane];
            m0 = (accA.x + accB.x + accC.x + accD.x + dc * xc.x) * sc;
            m1 = (accA.y + accB.y + accC.y + accD.y + dc * xc.y) * sc;
            m2 = (accA.z + accB.z + accC.z + accD.z + dc * xc.z) * sc;
            m3 = (accA.w + accB.w + accC.w + accD.w + dc * xc.w) * sc;
        }
        int g   = r_loc >> 4;
        int w16 = r_loc & 15;
        int gd  = w16 & 7;
        int rh  = w16 >> 3;
#pragma unroll
        for (int p = 0; p < 2; p++) {
            int cp = 2 * lane + p;
            int q  = cp >> 3;
            int w8 = cp & 7;
            int tcc = w8 & 3;
            int kh  = w8 >> 2;
            int tw = (gd * 4 + tcc) * 4 + kh * 2 + rh;
            uint2 sm = (p == 0) ? split_bf2(m0, m1) : split_bf2(m2, m3);
            unsigned sxh = (p == 0) ? pack_bf2(xc.x, xc.y) : pack_bf2(xc.z, xc.w);
            stgbuf[stg_i(0, q, g, tw)] = sm.x;
            stgbuf[stg_i(1, q, g, tw)] = sm.y;
            stgbuf[stg_i(2, q, g, tw)] = sxh;
        }
    }
}

// ---------- persistent fused: pipelined gather + 2 HMMA GEMMs + gate + LN ----------
__global__ void __launch_bounds__(FTHREADS, 1)
fused_kernel(const float* __restrict__ x,
             const float* __restrict__ msg_b, const float* __restrict__ gate_b,
             const float* __restrict__ ln_g, const float* __restrict__ ln_b,
             float* __restrict__ out) {
    extern __shared__ char smem[];
    unsigned* sB   = (unsigned*)smem;                  // B frags (3 images)
    unsigned* stg  = (unsigned*)(smem + SMB_STG);      // 2 staging sets
    float* s_mb = (float*)(smem + SMB_MB);
    float* s_gb = (float*)(smem + SMB_GB);
    float* s_ga = (float*)(smem + SMB_GA);
    float* s_be = (float*)(smem + SMB_BE);
    float* s1   = (float*)(smem + SMB_S1);             // [8][64]
    float* s2   = (float*)(smem + SMB_S2);

    int tid  = threadIdx.x;
    int w    = tid >> 5, lane = tid & 31;
    int cg   = w >> 1;            // col group (16 cols)
    int rg   = w & 1;             // row group (32 rows of the 64-row half)
    int gid  = lane >> 2;
    int tc4  = lane & 3;

    int2* ebuf = (int2*)(smem + SMB_EBUF) + w * BUFCAP;   // per-warp edge buffer

    // load B images + biases (once)
    {
        const uint4* src = (const uint4*)g_wfrag;
        uint4* dst = (uint4*)sB;
#pragma unroll
        for (int i = 0; i < 12; i++) dst[tid + i * FTHREADS] = src[tid + i * FTHREADS];
        if (tid < 128) {
            s_mb[tid] = msg_b[tid];
            s_gb[tid] = gate_b[tid];
            s_ga[tid] = ln_g[tid];
            s_be[tid] = ln_b[tid];
        }
    }

    const float4* x4 = (const float4*)x;

    int myTiles = (NT_TILES - 1 - blockIdx.x) / FGRID + 1;
    int nh = 2 * myTiles;

    // prologue: gather half 0
    {
        int base0 = blockIdx.x * TILE_M;
        gather_half(base0, stg, ebuf, x4, w, lane);
    }
    __syncthreads();

#pragma unroll 1
    for (int k = 0; k < nh; k++) {
        unsigned* cur = stg + (k & 1) * PLANE_W;
        unsigned* nxt = stg + ((k + 1) & 1) * PLANE_W;
        int tile = blockIdx.x + (k >> 1) * FGRID;
        int base = tile * TILE_M + (k & 1) * 64;

        // ---- pipelined gather of NEXT half (other staging set) ----
        if (k + 1 < nh) {
            int tile1 = blockIdx.x + ((k + 1) >> 1) * FGRID;
            int base1 = tile1 * TILE_M + ((k + 1) & 1) * 64;
            gather_half(base1, nxt, ebuf, x4, w, lane);
        }

        // ---- prefetch epilogue residual h (independent of MMA; hides L2 latency) ----
        int rowbase = base + rg * 32;
        float2 hpre[2][2][2];      // [mt][nt][r0/r1]
#pragma unroll
        for (int mt = 0; mt < 2; mt++) {
            int r0 = rowbase + mt * 16 + gid;
            int r1 = r0 + 8;
#pragma unroll
            for (int nt = 0; nt < 2; nt++) {
                int c0 = cg * 16 + nt * 8 + 2 * tc4;
                hpre[mt][nt][0] = (r0 < N_NODES) ? *(const float2*)(x + (size_t)r0 * H + c0)
                                                 : make_float2(0.f, 0.f);
                hpre[mt][nt][1] = (r1 < N_NODES) ? *(const float2*)(x + (size_t)r1 * H + c0)
                                                 : make_float2(0.f, 0.f);
            }
        }

        // ---- MMA: 64 x 128 x 128; msg 3-term split, gate pure bf16 ----
        float acc_m[2][2][4], acc_g[2][2][4];
#pragma unroll
        for (int mt = 0; mt < 2; mt++)
#pragma unroll
            for (int nt = 0; nt < 2; nt++)
#pragma unroll
                for (int d = 0; d < 4; d++) { acc_m[mt][nt][d] = 0.f; acc_g[mt][nt][d] = 0.f; }

#pragma unroll 1
        for (int q = 0; q < 8; q++) {
            uint4 afr[2][3];
#pragma unroll
            for (int mt = 0; mt < 2; mt++)
#pragma unroll
                for (int v = 0; v < 3; v++)
                    afr[mt][v] = *(const uint4*)&cur[stg_i(v, q, rg * 2 + mt, lane * 4)];
#pragma unroll
            for (int nt = 0; nt < 2; nt++) {
                int gnt = cg * 2 + nt;
                uint2 bmh = *(const uint2*)(sB + (((0 * 8 + q) * 16 + gnt) * 32 + lane) * 2);
                uint2 bml = *(const uint2*)(sB + (((1 * 8 + q) * 16 + gnt) * 32 + lane) * 2);
                uint2 bgh = *(const uint2*)(sB + (((2 * 8 + q) * 16 + gnt) * 32 + lane) * 2);
#pragma unroll
                for (int mt = 0; mt < 2; mt++) {
                    mma16816(acc_m[mt][nt], (const unsigned*)&afr[mt][0], (const unsigned*)&bmh);
                    mma16816(acc_m[mt][nt], (const unsigned*)&afr[mt][0], (const unsigned*)&bml);
                    mma16816(acc_m[mt][nt], (const unsigned*)&afr[mt][1], (const unsigned*)&bmh);
                    mma16816(acc_g[mt][nt], (const unsigned*)&afr[mt][2], (const unsigned*)&bgh);
                }
            }
        }

        // ---- epilogue: gate + residual, partial LN sums ----
        float sum1[2][2] = {{0.f, 0.f}, {0.f, 0.f}};   // [mt][rhh]
        float sum2[2][2] = {{0.f, 0.f}, {0.f, 0.f}};
#pragma unroll
        for (int mt = 0; mt < 2; mt++) {
#pragma unroll
            for (int nt = 0; nt < 2; nt++) {
                int c0 = cg * 16 + nt * 8 + 2 * tc4;
                float2 h0 = hpre[mt][nt][0];
                float2 h1 = hpre[mt][nt][1];
                float mb0 = s_mb[c0], mb1 = s_mb[c0 + 1];
                float gb0 = s_gb[c0], gb1 = s_gb[c0 + 1];
                float* am = acc_m[mt][nt];
                float* ag = acc_g[mt][nt];
                float v0 = h0.x + (am[0] + mb0) / (1.f + __expf(-(ag[0] + gb0)));
                float v1 = h0.y + (am[1] + mb1) / (1.f + __expf(-(ag[1] + gb1)));
                float v2 = h1.x + (am[2] + mb0) / (1.f + __expf(-(ag[2] + gb0)));
                float v3 = h1.y + (am[3] + mb1) / (1.f + __expf(-(ag[3] + gb1)));
                am[0] = v0; am[1] = v1; am[2] = v2; am[3] = v3;
                sum1[mt][0] += v0 + v1;  sum2[mt][0] += v0 * v0 + v1 * v1;
                sum1[mt][1] += v2 + v3;  sum2[mt][1] += v2 * v2 + v3 * v3;
            }
        }
#pragma unroll
        for (int mt = 0; mt < 2; mt++)
#pragma unroll
            for (int rr = 0; rr < 2; rr++) {
                sum1[mt][rr] += __shfl_xor_sync(0xffffffffu, sum1[mt][rr], 1);
                sum1[mt][rr] += __shfl_xor_sync(0xffffffffu, sum1[mt][rr], 2);
                sum2[mt][rr] += __shfl_xor_sync(0xffffffffu, sum2[mt][rr], 1);
                sum2[mt][rr] += __shfl_xor_sync(0xffffffffu, sum2[mt][rr], 2);
            }
        if (tc4 == 0) {
#pragma unroll
            for (int mt = 0; mt < 2; mt++)
#pragma unroll
                for (int rr = 0; rr < 2; rr++) {
                    int rl = rg * 32 + mt * 16 + gid + rr * 8;
                    s1[cg * 64 + rl] = sum1[mt][rr];
                    s2[cg * 64 + rl] = sum2[mt][rr];
                }
        }
        __syncthreads();

        // ---- LN finalize + store ----
        float mu_[2][2], ri_[2][2];
#pragma unroll
        for (int mt = 0; mt < 2; mt++)
#pragma unroll
            for (int rr = 0; rr < 2; rr++) {
                int rl = rg * 32 + mt * 16 + gid + rr * 8;
                float S = 0.f, S2 = 0.f;
#pragma unroll
                for (int c = 0; c < 8; c++) { S += s1[c * 64 + rl]; S2 += s2[c * 64 + rl]; }
                float mu = S * (1.f / (float)H);
                float var = S2 * (1.f / (float)H) - mu * mu;
                mu_[mt][rr] = mu;
                ri_[mt][rr] = rsqrtf(var + LN_EPS);
            }
#pragma unroll
        for (int mt = 0; mt < 2; mt++) {
            int r0 = rowbase + mt * 16 + gid;
            int r1 = r0 + 8;
#pragma unroll
            for (int nt = 0; nt < 2; nt++) {
                int c0 = cg * 16 + nt * 8 + 2 * tc4;
                float ga0 = s_ga[c0], ga1 = s_ga[c0 + 1];
                float be0 = s_be[c0], be1 = s_be[c0 + 1];
                float* am = acc_m[mt][nt];
                if (r0 < N_NODES) {
                    float2 o;
                    o.x = (am[0] - mu_[mt][0]) * ri_[mt][0] * ga0 + be0;
                    o.y = (am[1] - mu_[mt][0]) * ri_[mt][0] * ga1 + be1;
                    *(float2*)(out + (size_t)r0 * H + c0) = o;
                }
                if (r1 < N_NODES) {
                    float2 o;
                    o.x = (am[2] - mu_[mt][1]) * ri_[mt][1] * ga0 + be0;
                    o.y = (am[3] - mu_[mt][1]) * ri_[mt][1] * ga1 + be1;
                    *(float2*)(out + (size_t)r1 * H + c0) = o;
                }
            }
        }
        __syncthreads();   // staging(next) complete + partials reuse safety
    }
}

// ---------- launch ----------
extern "C" void kernel_launch(void* const* d_in, const int* in_sizes, int n_in,
                              void* d_out, int out_size) {
    const float* x      = (const float*)d_in[0];
    const int*   ei     = (const int*)d_in[1];
    const float* msg_W  = (const float*)d_in[2];
    const float* msg_b  = (const float*)d_in[3];
    const float* msg_A  = (const float*)d_in[4];
    const float* msg_B  = (const float*)d_in[5];
    const float* gate_W = (const float*)d_in[6];
    const float* gate_b = (const float*)d_in[7];
    const float* gate_A = (const float*)d_in[8];
    const float* gate_B = (const float*)d_in[9];
    const float* ln_g   = (const float*)d_in[10];
    const float* ln_b   = (const float*)d_in[11];
    float* out = (float*)d_out;

    const int* rows = ei;
    const int* cols = ei + N_EDGES;

    weff_kernel<<<H, H>>>(msg_W, msg_A, msg_B, gate_W, gate_A, gate_B);
    hist_kernel<<<(N_EDGES + 255) / 256, 256>>>(cols);
    scan_pass1<<<SCAN_NB, SCAN_CHUNK>>>();
    scan_pass2<<<1, 256>>>();
    scan_pass3<<<SCAN_NB, SCAN_CHUNK>>>();
    scatter_kernel<<<(N_EDGES + 255) / 256, 256>>>(rows, cols);

    cudaFuncSetAttribute(fused_kernel, cudaFuncAttributeMaxDynamicSharedMemorySize, FUSED_SMEM);
    fused_kernel<<<FGRID, FTHREADS, FUSED_SMEM>>>(x, msg_b, gate_b, ln_g, ln_b, out);
}

// round 17
// speedup vs baseline: 1.2791x; 1.0381x over previous
#include <cuda_runtime.h>
#include <cuda_bf16.h>
#include <math.h>
#include <stdint.h>

#define N_NODES 100000
#define N_EDGES 600000
#define H 128
#define R 16
#define SCALING 2.0f
#define LN_EPS 1e-5f

#define SCAN_CHUNK 512
#define SCAN_NB ((N_NODES + SCAN_CHUNK - 1) / SCAN_CHUNK)   // 196

#define TILE_M 128
#define NT_TILES ((N_NODES + TILE_M - 1) / TILE_M)          // 782
#define FGRID 148
#define FTHREADS 1024

#define QPAD 516                      // words per (v,q) staging plane (4*128 + 4 pad)
#define PLANE_W (3 * 8 * QPAD)        // words per staging set = 12384 (49536 B)
#define BUFCAP 64                     // edge records per warp buffer (2 nodes/warp)

// fused smem layout (bytes): 3 weight images + 2x staging sets + edge buffer
#define SMB_W    0                    // 3 x 32KB = 98304
#define SMB_STG  98304                // 2 x 49536 = 99072
#define SMB_MB   197376
#define SMB_GB   197888
#define SMB_GA   198400
#define SMB_BE   198912
#define SMB_S1   199424               // [8][64] f32
#define SMB_S2   201472
#define SMB_EBUF 203520               // 32 warps x 64 int2 = 16384
#define FUSED_SMEM 219904

// ---------- static device scratch ----------
__device__ int   g_deg[N_NODES];      // zero-init; scatter restores to zero each call
__device__ int   g_off[N_NODES + 1];
__device__ float g_dinv[N_NODES];
__device__ int2  g_erec[N_EDGES];     // packed (src, __float_as_int(dinv[src]))
__device__ int   g_bsum[256];
// B fragments: [v 3][q 8][nt 16][T 32][b0,b1] u32 = 96 KB (msg_hi, msg_lo, gate_hi)
__device__ unsigned g_wfrag[3 * 8 * 16 * 32 * 2];

// ---------- helpers ----------
__device__ __forceinline__ unsigned pack_bf2(float e0, float e1) {
    unsigned r;
    asm("cvt.rn.bf16x2.f32 %0, %1, %2;" : "=r"(r) : "f"(e1), "f"(e0));  // lo=e0, hi=e1
    return r;
}
__device__ __forceinline__ uint2 split_bf2(float e0, float e1) {
    unsigned hi = pack_bf2(e0, e1);
    float h0 = __uint_as_float(hi << 16);
    float h1 = __uint_as_float(hi & 0xffff0000u);
    unsigned lo = pack_bf2(e0 - h0, e1 - h1);
    return make_uint2(hi, lo);
}
__device__ __forceinline__ void mma16816(float* d, const unsigned* a, const unsigned* b) {
    asm volatile(
        "mma.sync.aligned.m16n8k16.row.col.f32.bf16.bf16.f32 "
        "{%0,%1,%2,%3}, {%4,%5,%6,%7}, {%8,%9}, {%0,%1,%2,%3};"
        : "+f"(d[0]), "+f"(d[1]), "+f"(d[2]), "+f"(d[3])
        : "r"(a[0]), "r"(a[1]), "r"(a[2]), "r"(a[3]), "r"(b[0]), "r"(b[1]));
}
__device__ __forceinline__ int stg_i(int v, int q, int g, int tw) {
    return (v * 8 + q) * QPAD + g * 128 + tw;
}

// ---------- 1. in-degree histogram ----------
__global__ void hist_kernel(const int* __restrict__ col) {
    int e = blockIdx.x * blockDim.x + threadIdx.x;
    if (e < N_EDGES) atomicAdd(&g_deg[col[e]], 1);
}

// ---------- 2. parallel 3-pass scan (coalesced) ----------
__global__ void scan_pass1() {
    __shared__ int sh[SCAN_CHUNK];
    int i = blockIdx.x * SCAN_CHUNK + threadIdx.x;
    sh[threadIdx.x] = (i < N_NODES) ? g_deg[i] : 0;
    __syncthreads();
    for (int off = SCAN_CHUNK / 2; off > 0; off >>= 1) {
        if (threadIdx.x < off) sh[threadIdx.x] += sh[threadIdx.x + off];
        __syncthreads();
    }
    if (threadIdx.x == 0) g_bsum[blockIdx.x] = sh[0];
}
__global__ void scan_pass2() {       // shfl two-level scan over 196 block sums
    __shared__ int wsum[8];
    int t = threadIdx.x;             // 256 threads = 8 warps
    int lane = t & 31, wid = t >> 5;
    int v = (t < SCAN_NB) ? g_bsum[t] : 0;
    int s = v;
#pragma unroll
    for (int off = 1; off < 32; off <<= 1) {
        int n = __shfl_up_sync(0xffffffffu, s, off);
        if (lane >= off) s += n;
    }
    if (lane == 31) wsum[wid] = s;
    __syncthreads();
    if (wid == 0) {
        int ws = (lane < 8) ? wsum[lane] : 0;
#pragma unroll
        for (int off = 1; off < 8; off <<= 1) {
            int n = __shfl_up_sync(0xffffffffu, ws, off);
            if (lane >= off) ws += n;
        }
        if (lane < 8) wsum[lane] = ws;
    }
    __syncthreads();
    int pre = s - v + (wid > 0 ? wsum[wid - 1] : 0);   // exclusive prefix
    if (t < SCAN_NB) g_bsum[t] = pre;
    if (t == 255) g_off[N_NODES] = pre + v;
}
__global__ void scan_pass3() {       // + dinv folded in
    __shared__ int sh[SCAN_CHUNK];
    int i = blockIdx.x * SCAN_CHUNK + threadIdx.x;
    int v = (i < N_NODES) ? g_deg[i] : 0;
    sh[threadIdx.x] = v;
    __syncthreads();
    for (int off = 1; off < SCAN_CHUNK; off <<= 1) {
        int t = (threadIdx.x >= off) ? sh[threadIdx.x - off] : 0;
        __syncthreads();
        sh[threadIdx.x] += t;
        __syncthreads();
    }
    if (i < N_NODES) {
        g_off[i]  = g_bsum[blockIdx.x] + sh[threadIdx.x] - v;
        g_dinv[i] = rsqrtf((float)(v + 1));
    }
}

// ---------- 3. bucket edges by target; records (src, dinv[src]); zeroes g_deg ----------
__global__ void scatter_kernel(const int* __restrict__ row, const int* __restrict__ col) {
    int e = blockIdx.x * blockDim.x + threadIdx.x;
    if (e < N_EDGES) {
        int c = col[e];
        int r = row[e];
        int p = atomicAdd(&g_deg[c], -1) - 1;    // restores g_deg to 0
        g_erec[g_off[c] + p] = make_int2(r, __float_as_int(g_dinv[r]));
    }
}

// ---------- 0. effective weights -> B-fragment images (msg hi/lo, gate hi) ----------
__global__ void weff_kernel(const float* __restrict__ msg_W, const float* __restrict__ msg_A,
                            const float* __restrict__ msg_B,
                            const float* __restrict__ gate_W, const float* __restrict__ gate_A,
                            const float* __restrict__ gate_B) {
    int k = blockIdx.x;          // input feature 0..127
    int j = threadIdx.x;         // output feature 0..127
    __shared__ float sam[R], sag[R];
    if (j < R) { sam[j] = msg_A[j * H + k]; sag[j] = gate_A[j * H + k]; }
    __syncthreads();
    float am = 0.f, ag = 0.f;
#pragma unroll
    for (int r = 0; r < R; r++) {
        am += msg_B[j * R + r] * sam[r];
        ag += gate_B[j * R + r] * sag[r];
    }
    float wm = msg_W[j * H + k] + SCALING * am;
    float wg = gate_W[j * H + k] + SCALING * ag;

    int q  = k >> 4, k2 = k & 15;
    int nt = j >> 3, n  = j & 7;
    int T  = n * 4 + ((k2 & 7) >> 1);
    int reg = k2 >> 3, half = k2 & 1;
    int idx = ((q * 16 + nt) * 32 + T) * 4 + reg * 2 + half;  // u16 within variant
    int vstride = 8 * 16 * 32 * 4;

    unsigned short* img = (unsigned short*)g_wfrag;
    __nv_bfloat16 mh = __float2bfloat16(wm);
    __nv_bfloat16 ml = __float2bfloat16(wm - __bfloat162float(mh));
    __nv_bfloat16 gh = __float2bfloat16(wg);
    img[0 * vstride + idx] = *(unsigned short*)&mh;
    img[1 * vstride + idx] = *(unsigned short*)&ml;
    img[2 * vstride + idx] = *(unsigned short*)&gh;
}

// ---------- gather one 64-row half into a staging set (2 nodes per warp) ----------
__device__ __forceinline__ void gather_half(
    int base, unsigned* stgbuf, int2* ebuf,
    const float4* __restrict__ x4, int w, int lane)
{
    int n0  = base + w * 2;
    int n0c = (n0     < N_NODES) ? n0     : N_NODES;
    int n2c = (n0 + 2 < N_NODES) ? n0 + 2 : N_NODES;
    int begAll = g_off[n0c];
    int endAll = g_off[n2c];
    int cnt    = endAll - begAll;
    bool fast  = (cnt <= BUFCAP);
    __syncwarp();                       // WAR: prior reads of ebuf done
    if (fast) {
        if (lane < cnt)      ebuf[lane]      = g_erec[begAll + lane];
        if (lane + 32 < cnt) ebuf[lane + 32] = g_erec[begAll + lane + 32];
        __syncwarp();
    }
#pragma unroll 1
    for (int i = 0; i < 2; i++) {
        int r_loc = w * 2 + i;
        int node  = base + r_loc;
        float4 xc = make_float4(0.f, 0.f, 0.f, 0.f);
        float m0 = 0.f, m1 = 0.f, m2 = 0.f, m3 = 0.f;
        if (node < N_NODES) {
            float4 accA = make_float4(0.f, 0.f, 0.f, 0.f);
            float4 accB = make_float4(0.f, 0.f, 0.f, 0.f);
            float4 accC = make_float4(0.f, 0.f, 0.f, 0.f);
            float4 accD = make_float4(0.f, 0.f, 0.f, 0.f);
            int beg = g_off[node], end = g_off[node + 1];
            if (fast) {
                int jb = beg - begAll, je = end - begAll;
#pragma unroll 1
                for (int j = jb; j < je; j += 4) {
                    int2 rA = ebuf[j];
                    int2 rB = (j + 1 < je) ? ebuf[j + 1] : make_int2(0, 0);
                    int2 rC = (j + 2 < je) ? ebuf[j + 2] : make_int2(0, 0);
                    int2 rD = (j + 3 < je) ? ebuf[j + 3] : make_int2(0, 0);
                    float4 vA = x4[rA.x * 32 + lane];
                    float4 vB = x4[rB.x * 32 + lane];
                    float4 vC = x4[rC.x * 32 + lane];
                    float4 vD = x4[rD.x * 32 + lane];
                    float wA = __int_as_float(rA.y), wB = __int_as_float(rB.y);
                    float wC = __int_as_float(rC.y), wD = __int_as_float(rD.y);
                    accA.x += wA * vA.x; accA.y += wA * vA.y; accA.z += wA * vA.z; accA.w += wA * vA.w;
                    accB.x += wB * vB.x; accB.y += wB * vB.y; accB.z += wB * vB.z; accB.w += wB * vB.w;
                    accC.x += wC * vC.x; accC.y += wC * vC.y; accC.z += wC * vC.z; accC.w += wC * vC.w;
                    accD.x += wD * vD.x; accD.y += wD * vD.y; accD.z += wD * vD.z; accD.w += wD * vD.w;
                }
            } else {
#pragma unroll 1
                for (int e = beg; e < end; e += 2) {
                    int2 rA = g_erec[e];
                    int2 rB = (e + 1 < end) ? g_erec[e + 1] : make_int2(0, 0);
                    float4 vA = x4[rA.x * 32 + lane];
                    float4 vB = x4[rB.x * 32 + lane];
                    float wA = __int_as_float(rA.y), wB = __int_as_float(rB.y);
                    accA.x += wA * vA.x; accA.y += wA * vA.y; accA.z += wA * vA.z; accA.w += wA * vA.w;
                    accB.x += wB * vB.x; accB.y += wB * vB.y; accB.z += wB * vB.z; accB.w += wB * vB.w;
                }
            }
            float dc = g_dinv[node];
            float sc = dc / (float)(end - beg + 1);
            xc = x4[node * 32 + lane];
            m0 = (accA.x + accB.x + accC.x + accD.x + dc * xc.x) * sc;
            m1 = (accA.y + accB.y + accC.y + accD.y + dc * xc.y) * sc;
            m2 = (accA.z + accB.z + accC.z + accD.z + dc * xc.z) * sc;
            m3 = (accA.w + accB.w + accC.w + accD.w + dc * xc.w) * sc;
        }
        int g   = r_loc >> 4;
        int w16 = r_loc & 15;
        int gd  = w16 & 7;
        int rh  = w16 >> 3;
#pragma unroll
        for (int p = 0; p < 2; p++) {
            int cp = 2 * lane + p;
            int q  = cp >> 3;
            int w8 = cp & 7;
            int tcc = w8 & 3;
            int kh  = w8 >> 2;
            int tw = (gd * 4 + tcc) * 4 + kh * 2 + rh;
            uint2 sm = (p == 0) ? split_bf2(m0, m1) : split_bf2(m2, m3);
            unsigned sxh = (p == 0) ? pack_bf2(xc.x, xc.y) : pack_bf2(xc.z, xc.w);
            stgbuf[stg_i(0, q, g, tw)] = sm.x;
            stgbuf[stg_i(1, q, g, tw)] = sm.y;
            stgbuf[stg_i(2, q, g, tw)] = sxh;
        }
    }
}

// ---------- persistent fused: pipelined gather + 2 HMMA GEMMs + gate + LN ----------
__global__ void __launch_bounds__(FTHREADS, 1)
fused_kernel(const float* __restrict__ x,
             const float* __restrict__ msg_b, const float* __restrict__ gate_b,
             const float* __restrict__ ln_g, const float* __restrict__ ln_b,
             float* __restrict__ out) {
    extern __shared__ char smem[];
    unsigned* sB   = (unsigned*)smem;                  // B frags (3 images)
    unsigned* stg  = (unsigned*)(smem + SMB_STG);      // 2 staging sets
    float* s_mb = (float*)(smem + SMB_MB);
    float* s_gb = (float*)(smem + SMB_GB);
    float* s_ga = (float*)(smem + SMB_GA);
    float* s_be = (float*)(smem + SMB_BE);
    float* s1   = (float*)(smem + SMB_S1);             // [8][64]
    float* s2   = (float*)(smem + SMB_S2);

    int tid  = threadIdx.x;
    int w    = tid >> 5, lane = tid & 31;   // 32 warps
    int rgq  = w & 3;             // row group (16 rows of the 64-row half)
    int cgq  = w >> 2;            // col group (16 cols), 0..7
    int gid  = lane >> 2;
    int tc4  = lane & 3;

    int2* ebuf = (int2*)(smem + SMB_EBUF) + w * BUFCAP;   // per-warp edge buffer

    // load B images + biases (once)
    {
        const uint4* src = (const uint4*)g_wfrag;
        uint4* dst = (uint4*)sB;
#pragma unroll
        for (int i = 0; i < 6; i++) dst[tid + i * FTHREADS] = src[tid + i * FTHREADS];
        if (tid < 128) {
            s_mb[tid] = msg_b[tid];
            s_gb[tid] = gate_b[tid];
            s_ga[tid] = ln_g[tid];
            s_be[tid] = ln_b[tid];
        }
    }

    const float4* x4 = (const float4*)x;

    int myTiles = (NT_TILES - 1 - blockIdx.x) / FGRID + 1;
    int nh = 2 * myTiles;

    // prologue: gather half 0
    {
        int base0 = blockIdx.x * TILE_M;
        gather_half(base0, stg, ebuf, x4, w, lane);
    }
    __syncthreads();

#pragma unroll 1
    for (int k = 0; k < nh; k++) {
        unsigned* cur = stg + (k & 1) * PLANE_W;
        unsigned* nxt = stg + ((k + 1) & 1) * PLANE_W;
        int tile = blockIdx.x + (k >> 1) * FGRID;
        int base = tile * TILE_M + (k & 1) * 64;

        // ---- pipelined gather of NEXT half (other staging set) ----
        if (k + 1 < nh) {
            int tile1 = blockIdx.x + ((k + 1) >> 1) * FGRID;
            int base1 = tile1 * TILE_M + ((k + 1) & 1) * 64;
            gather_half(base1, nxt, ebuf, x4, w, lane);
        }

        // ---- prefetch epilogue residual h (independent of MMA) ----
        int rowbase = base + rgq * 16;
        int r0 = rowbase + gid;
        int r1 = r0 + 8;
        float2 hpre[2][2];         // [nt][r0/r1]
#pragma unroll
        for (int nt = 0; nt < 2; nt++) {
            int c0 = cgq * 16 + nt * 8 + 2 * tc4;
            hpre[nt][0] = (r0 < N_NODES) ? *(const float2*)(x + (size_t)r0 * H + c0)
                                         : make_float2(0.f, 0.f);
            hpre[nt][1] = (r1 < N_NODES) ? *(const float2*)(x + (size_t)r1 * H + c0)
                                         : make_float2(0.f, 0.f);
        }

        // ---- MMA: 16 rows x 16 cols per warp; msg 3-term split, gate bf16 ----
        float acc_m[2][4], acc_g[2][4];
#pragma unroll
        for (int nt = 0; nt < 2; nt++)
#pragma unroll
            for (int d = 0; d < 4; d++) { acc_m[nt][d] = 0.f; acc_g[nt][d] = 0.f; }

#pragma unroll 1
        for (int q = 0; q < 8; q++) {
            uint4 afr[3];
#pragma unroll
            for (int v = 0; v < 3; v++)
                afr[v] = *(const uint4*)&cur[stg_i(v, q, rgq, lane * 4)];
#pragma unroll
            for (int nt = 0; nt < 2; nt++) {
                int gnt = cgq * 2 + nt;
                uint2 bmh = *(const uint2*)(sB + (((0 * 8 + q) * 16 + gnt) * 32 + lane) * 2);
                uint2 bml = *(const uint2*)(sB + (((1 * 8 + q) * 16 + gnt) * 32 + lane) * 2);
                uint2 bgh = *(const uint2*)(sB + (((2 * 8 + q) * 16 + gnt) * 32 + lane) * 2);
                mma16816(acc_m[nt], (const unsigned*)&afr[0], (const unsigned*)&bmh);
                mma16816(acc_m[nt], (const unsigned*)&afr[0], (const unsigned*)&bml);
                mma16816(acc_m[nt], (const unsigned*)&afr[1], (const unsigned*)&bmh);
                mma16816(acc_g[nt], (const unsigned*)&afr[2], (const unsigned*)&bgh);
            }
        }

        // ---- epilogue: gate + residual, partial LN sums ----
        float sum1[2] = {0.f, 0.f};    // [r0/r1]
        float sum2[2] = {0.f, 0.f};
#pragma unroll
        for (int nt = 0; nt < 2; nt++) {
            int c0 = cgq * 16 + nt * 8 + 2 * tc4;
            float2 h0 = hpre[nt][0];
            float2 h1 = hpre[nt][1];
            float mb0 = s_mb[c0], mb1 = s_mb[c0 + 1];
            float gb0 = s_gb[c0], gb1 = s_gb[c0 + 1];
            float* am = acc_m[nt];
            float* ag = acc_g[nt];
            float v0 = h0.x + (am[0] + mb0) / (1.f + __expf(-(ag[0] + gb0)));
            float v1 = h0.y + (am[1] + mb1) / (1.f + __expf(-(ag[1] + gb1)));
            float v2 = h1.x + (am[2] + mb0) / (1.f + __expf(-(ag[2] + gb0)));
            float v3 = h1.y + (am[3] + mb1) / (1.f + __expf(-(ag[3] + gb1)));
            am[0] = v0; am[1] = v1; am[2] = v2; am[3] = v3;
            sum1[0] += v0 + v1;  sum2[0] += v0 * v0 + v1 * v1;
            sum1[1] += v2 + v3;  sum2[1] += v2 * v2 + v3 * v3;
        }
#pragma unroll
        for (int rr = 0; rr < 2; rr++) {
            sum1[rr] += __shfl_xor_sync(0xffffffffu, sum1[rr], 1);
            sum1[rr] += __shfl_xor_sync(0xffffffffu, sum1[rr], 2);
            sum2[rr] += __shfl_xor_sync(0xffffffffu, sum2[rr], 1);
            sum2[rr] += __shfl_xor_sync(0xffffffffu, sum2[rr], 2);
        }
        if (tc4 == 0) {
#pragma unroll
            for (int rr = 0; rr < 2; rr++) {
                int rl = rgq * 16 + gid + rr * 8;
                s1[cgq * 64 + rl] = sum1[rr];
                s2[cgq * 64 + rl] = sum2[rr];
            }
        }
        __syncthreads();

        // ---- LN finalize + store ----
        float mu_[2], ri_[2];
#pragma unroll
        for (int rr = 0; rr < 2; rr++) {
            int rl = rgq * 16 + gid + rr * 8;
            float S = 0.f, S2 = 0.f;
#pragma unroll
            for (int c = 0; c < 8; c++) { S += s1[c * 64 + rl]; S2 += s2[c * 64 + rl]; }
            float mu = S * (1.f / (float)H);
            float var = S2 * (1.f / (float)H) - mu * mu;
            mu_[rr] = mu;
            ri_[rr] = rsqrtf(var + LN_EPS);
        }
#pragma unroll
        for (int nt = 0; nt < 2; nt++) {
            int c0 = cgq * 16 + nt * 8 + 2 * tc4;
            float ga0 = s_ga[c0], ga1 = s_ga[c0 + 1];
            float be0 = s_be[c0], be1 = s_be[c0 + 1];
            float* am = acc_m[nt];
            if (r0 < N_NODES) {
                float2 o;
                o.x = (am[0] - mu_[0]) * ri_[0] * ga0 + be0;
                o.y = (am[1] - mu_[0]) * ri_[0] * ga1 + be1;
                *(float2*)(out + (size_t)r0 * H + c0) = o;
            }
            if (r1 < N_NODES) {
                float2 o;
                o.x = (am[2] - mu_[1]) * ri_[1] * ga0 + be0;
                o.y = (am[3] - mu_[1]) * ri_[1] * ga1 + be1;
                *(float2*)(out + (size_t)r1 * H + c0) = o;
            }
        }
        __syncthreads();   // staging(next) complete + partials reuse safety
    }
}

// ---------- launch ----------
extern "C" void kernel_launch(void* const* d_in, const int* in_sizes, int n_in,
                              void* d_out, int out_size) {
    const float* x      = (const float*)d_in[0];
    const int*   ei     = (const int*)d_in[1];
    const float* msg_W  = (const float*)d_in[2];
    const float* msg_b  = (const float*)d_in[3];
    const float* msg_A  = (const float*)d_in[4];
    const float* msg_B  = (const float*)d_in[5];
    const float* gate_W = (const float*)d_in[6];
    const float* gate_b = (const float*)d_in[7];
    const float* gate_A = (const float*)d_in[8];
    const float* gate_B = (const float*)d_in[9];
    const float* ln_g   = (const float*)d_in[10];
    const float* ln_b   = (const float*)d_in[11];
    float* out = (float*)d_out;

    const int* rows = ei;
    const int* cols = ei + N_EDGES;

    weff_kernel<<<H, H>>>(msg_W, msg_A, msg_B, gate_W, gate_A, gate_B);
    hist_kernel<<<(N_EDGES + 255) / 256, 256>>>(cols);
    scan_pass1<<<SCAN_NB, SCAN_CHUNK>>>();
    scan_pass2<<<1, 256>>>();
    scan_pass3<<<SCAN_NB, SCAN_CHUNK>>>();
    scatter_kernel<<<(N_EDGES + 255) / 256, 256>>>(rows, cols);

    cudaFuncSetAttribute(fused_kernel, cudaFuncAttributeMaxDynamicSharedMemorySize, FUSED_SMEM);
    fused_kernel<<<FGRID, FTHREADS, FUSED_SMEM>>>(x, msg_b, gate_b, ln_g, ln_b, out);
}